// round 16
// baseline (speedup 1.0000x reference)
#include <cuda_runtime.h>
#include <cuda_bf16.h>

// IndRNN, 2 layers fused:
//   layer i: h_t = relu(x_t + h_{t-1} * w_i)   (elementwise over (b,h))
// Each (b,h) chain is independent -> 1 thread per chain, both layers carried
// in registers, single streaming pass over time. Deep register prefetch
// pipeline to hide DRAM latency at very low occupancy (16384 threads total).

#define TT 2048
#define BB 32
#define HH 512
#define BH (BB * HH)

__device__ __forceinline__ float relu_fma(float h, float w, float x) {
    return fmaxf(fmaf(h, w, x), 0.0f);
}

__global__ void __launch_bounds__(128, 1)
indrnn_fused_fast(const float* __restrict__ x,
                  const float* __restrict__ w,
                  const float* __restrict__ h0,
                  float* __restrict__ out) {
    const int idx = blockIdx.x * blockDim.x + threadIdx.x; // (b,h) chain id
    if (idx >= BH) return;
    const int h = idx & (HH - 1);

    const float w1 = w[h];
    const float w2 = w[HH + h];
    float h1 = h0[idx];
    float h2 = h0[BH + idx];

    const float* xp = x + idx;
    float*       op = out + idx;

    constexpr int U    = 16;          // steps per stage
    constexpr int PIPE = 4;           // stages in flight
    constexpr int STEP = U * PIPE;    // 64 steps per outer iteration
    static_assert(TT % STEP == 0, "T divisible by pipeline step");

    float buf[PIPE][U];

    // Prologue: fill the pipeline (64 outstanding streaming loads / thread).
#pragma unroll
    for (int p = 0; p < PIPE; ++p) {
#pragma unroll
        for (int i = 0; i < U; ++i) {
            buf[p][i] = __ldcs(xp + (size_t)(p * U + i) * BH);
        }
    }

#pragma unroll 1
    for (int t = 0; t < TT; t += STEP) {
#pragma unroll
        for (int p = 0; p < PIPE; ++p) {
            // Issue next stage's loads first (independent of the FMA chain);
            // consumed PIPE stages (= STEP timesteps) later.
            const int tl = t + STEP + p * U;
            const bool live = (tl < TT);
            float nxt[U];
#pragma unroll
            for (int i = 0; i < U; ++i) {
                nxt[i] = live ? __ldcs(xp + (size_t)(tl + i) * BH) : 0.0f;
            }

            // Serial recurrence on already-resident data.
            const int tb = t + p * U;
#pragma unroll
            for (int i = 0; i < U; ++i) {
                h1 = relu_fma(h1, w1, buf[p][i]);
                h2 = relu_fma(h2, w2, h1);
                __stcs(op + (size_t)(tb + i) * BH, h2);
            }

#pragma unroll
            for (int i = 0; i < U; ++i) buf[p][i] = nxt[i];
        }
    }
}

// Generic fallback for unexpected shapes (still fused 2-layer, no prefetch).
__global__ void indrnn_fused_generic(const float* __restrict__ x,
                                     const float* __restrict__ w,
                                     const float* __restrict__ h0,
                                     float* __restrict__ out,
                                     int T, int B, int H) {
    const int bh = B * H;
    for (int idx = blockIdx.x * blockDim.x + threadIdx.x; idx < bh;
         idx += gridDim.x * blockDim.x) {
        const int hc = idx % H;
        const float w1 = w[hc];
        const float w2 = w[H + hc];
        float h1 = h0[idx];
        float h2 = h0[bh + idx];
        const float* xp = x + idx;
        float*       op = out + idx;
        for (int t = 0; t < T; ++t) {
            h1 = relu_fma(h1, w1, __ldcs(xp + (size_t)t * bh));
            h2 = relu_fma(h2, w2, h1);
            __stcs(op + (size_t)t * bh, h2);
        }
    }
}

extern "C" void kernel_launch(void* const* d_in, const int* in_sizes, int n_in,
                              void* d_out, int out_size) {
    const float* x  = (const float*)d_in[0];  // [T, B, H]
    const float* w  = (const float*)d_in[1];  // [2, H]
    const float* h0 = (const float*)d_in[2];  // [2, B, H]
    float* out = (float*)d_out;               // [T, B, H]

    // Recover dims: in_sizes[1] = 2*H, in_sizes[2] = 2*B*H, in_sizes[0] = T*B*H
    const int H = in_sizes[1] / 2;
    const int B = (H > 0) ? in_sizes[2] / (2 * H) : 0;
    const int bh = B * H;
    const int T = (bh > 0) ? in_sizes[0] / bh : 0;

    if (T == TT && B == BB && H == HH) {
        indrnn_fused_fast<<<BH / 128, 128>>>(x, w, h0, out);
    } else {
        int threads = 128;
        int blocks = (bh + threads - 1) / threads;
        if (blocks < 1) blocks = 1;
        indrnn_fused_generic<<<blocks, threads>>>(x, w, h0, out, T, B, H);
    }
}